// round 3
// baseline (speedup 1.0000x reference)
#include <cuda_runtime.h>
#include <math.h>

#define B   8
#define C   128
#define HWD 128
#define L   41
#define CI  256
#define PLANE (HWD*HWD)

// ---------------- device scratch (no cudaMalloc allowed) ----------------
__device__ float g_fuse[(size_t)B*C*PLANE];   // 67 MB conv output
__device__ float g_sum_d[B*L*C];
__device__ float g_sum_f[B*L*C];
__device__ int   g_cnt[B*L];
__device__ float g_gd[B*C];
__device__ float g_gf[B*C];

// ---------------- f32x2 packed-FMA helpers (B300) ----------------
__device__ __forceinline__ unsigned long long pack2(float a, float b){
    unsigned long long r;
    asm("mov.b64 %0, {%1,%2};" : "=l"(r) : "f"(a), "f"(b));
    return r;
}
__device__ __forceinline__ void fma2(unsigned long long &d,
                                     unsigned long long a, unsigned long long b){
    asm("fma.rn.f32x2 %0, %1, %2, %0;" : "+l"(d) : "l"(a), "l"(b));
}
__device__ __forceinline__ void unpack2(unsigned long long v, float &lo, float &hi){
    asm("mov.b64 {%0,%1}, %2;" : "=f"(lo), "=f"(hi) : "l"(v));
}
__device__ __forceinline__ float sigmoidf(float x){
    return 1.0f / (1.0f + __expf(-x));
}

// ---------------- zero scratch (runs every replay) ----------------
__global__ void k_zero(){
    int i = blockIdx.x*256 + threadIdx.x;
    if (i < B*L*C){ g_sum_d[i] = 0.f; g_sum_f[i] = 0.f; }
    if (i < B*L)    g_cnt[i] = 0;
}

// ---------------- segment reduction (no hot-loop atomics) ----------------
// grid (8 row-tiles, B), block 256. which: 0 = d pass (+counts), 1 = fuse pass.
__global__ void k_seg(const float* __restrict__ feats_d,
                      const int*   __restrict__ label,
                      int which){
    __shared__ float ssum[2][L*C];          // 42 KB
    __shared__ unsigned char slab[2048];    // labels < 41
    __shared__ int scnt[L];
    int b    = blockIdx.y;
    int tile = blockIdx.x;
    int tid  = threadIdx.x;
    int c = tid & 127, h = tid >> 7;

    for (int i = tid; i < 2*L*C; i += 256) ((float*)ssum)[i] = 0.f;
    if (tid < L) scnt[tid] = 0;
    __syncthreads();

    int y0 = tile * 16;
    const int* lb = label + (size_t)b * 512 * 512;
    for (int p = tid; p < 2048; p += 256){
        int y = y0 + (p >> 7);
        int x = p & 127;
        int lv = lb[(y << 2) * 512 + (x << 2)];   // nearest resize: idx*4
        slab[p] = (unsigned char)lv;
        if (which == 0) atomicAdd(&scnt[lv], 1);
    }
    __syncthreads();

    const float* src = (which == 0) ? feats_d : g_fuse;
    const float* f = src + ((size_t)b*C + c) * PLANE + (size_t)y0 * HWD;
    float* sm = ssum[h];
    int pbase = h * 1024;
    #pragma unroll 4
    for (int i = 0; i < 1024; i += 4){
        int p = pbase + i;
        float4 v = *(const float4*)(f + p);
        sm[slab[p+0]*C + c] += v.x;
        sm[slab[p+1]*C + c] += v.y;
        sm[slab[p+2]*C + c] += v.z;
        sm[slab[p+3]*C + c] += v.w;
    }
    __syncthreads();

    float* sums = (which == 0) ? g_sum_d : g_sum_f;
    for (int i = tid; i < L*C; i += 256)
        atomicAdd(&sums[b*L*C + i], ssum[0][i] + ssum[1][i]);
    if (which == 0 && tid < L) atomicAdd(&g_cnt[b*L + tid], scnt[tid]);
}

// ---------------- gate: mean -> class L2-norm -> sum -> 2x 1x1 conv ----------------
// grid B, block 128 (thread = channel)
__global__ void k_gate(int which,
                       const float* __restrict__ base,
                       const float* __restrict__ w1,   // [8, C]
                       const float* __restrict__ w2){  // [C, 8]
    int b = blockIdx.x;
    int c = threadIdx.x;
    __shared__ float s_s[C];
    __shared__ float s_h[8];
    const float* sums = (which == 0) ? g_sum_d : g_sum_f;

    float sm = 0.f, n2 = 0.f;
    for (int l = 0; l < L; l++){
        int   cnt = g_cnt[b*L + l];
        float m;
        if (cnt > 0) m = sums[(b*L + l)*C + c] / (float)cnt;
        else         m = base[(b*L + l)*C + c];
        sm += m;
        n2 += m * m;
    }
    // att/=max(norm,eps); s = sum over classes  ==  sm / max(sqrt(n2), eps)
    s_s[c] = sm / fmaxf(sqrtf(n2), 1e-12f);
    __syncthreads();
    if (c < 8){
        float a = 0.f;
        for (int k = 0; k < C; k++) a += s_s[k] * w1[c*C + k];
        s_h[c] = fmaxf(a, 0.f);
    }
    __syncthreads();
    float a = 0.f;
    #pragma unroll
    for (int o = 0; o < 8; o++) a += s_h[o] * w2[c*8 + o];
    float g = sigmoidf(a);
    if (which == 0) g_gd[b*C + c] = g;
    else            g_gf[b*C + c] = g;
}

// ---------------- 3x3 conv (implicit concat, fp32 with packed f32x2 FMA) --------
// block: 16 out-ch x (8 rows x 128 cols); thread: 4 px x 16 co; grid (16, 8, B)
#define CO_T 16
#define CCH  8
__global__ __launch_bounds__(256, 2)
void k_conv(const float* __restrict__ r,
            const float* __restrict__ d,
            const float* __restrict__ w){
    __shared__ float xs[CCH][10][132];      // 42240 B
    __shared__ float ws[CCH*9*CO_T];        //  4608 B
    int tid  = threadIdx.x;
    int y0   = blockIdx.x * 8;
    int co0  = blockIdx.y * CO_T;
    int b    = blockIdx.z;
    int py   = tid >> 5;
    int px0  = (tid & 31) << 2;

    unsigned long long acc[4][8];
    #pragma unroll
    for (int p = 0; p < 4; p++)
        #pragma unroll
        for (int j = 0; j < 8; j++) acc[p][j] = 0ull;

    const float* rb = r + (size_t)b*C*PLANE;
    const float* db = d + (size_t)b*C*PLANE;

    for (int cc0 = 0; cc0 < CI; cc0 += CCH){
        __syncthreads();
        // weights chunk: [ci][k][co], 1152 elems
        for (int idx = tid; idx < CCH*9*CO_T; idx += 256){
            int co = idx & 15;
            int k  = (idx >> 4) % 9;
            int ci = idx / (16*9);
            ws[(ci*9 + k)*CO_T + co] = w[((size_t)(co0+co)*CI + cc0 + ci)*9 + k];
        }
        // input tile with halo: 8 x 10 x 130 elems; concat computed on the fly
        for (int idx = tid; idx < CCH*10*130; idx += 256){
            int ix = idx % 130;
            int iy = (idx / 130) % 10;
            int ci = idx / 1300;
            int gy = y0 + iy - 1;
            int gx = ix - 1;
            float v = 0.f;
            if ((unsigned)gy < 128u && (unsigned)gx < 128u){
                int cin = cc0 + ci;
                if (cin < C){
                    size_t o = (size_t)cin*PLANE + gy*HWD + gx;
                    v = rb[o] + db[o];
                } else {
                    size_t o = (size_t)(cin - C)*PLANE + gy*HWD + gx;
                    v = rb[o] * sigmoidf(db[o]);
                }
            }
            xs[ci][iy][ix] = v;
        }
        __syncthreads();

        #pragma unroll 2
        for (int ci = 0; ci < CCH; ci++){
            #pragma unroll
            for (int ky = 0; ky < 3; ky++){
                const float* xrow = &xs[ci][py + ky][px0];
                float xv[6];
                #pragma unroll
                for (int t = 0; t < 6; t++) xv[t] = xrow[t];
                #pragma unroll
                for (int kx = 0; kx < 3; kx++){
                    const unsigned long long* wp =
                        (const unsigned long long*)&ws[(ci*9 + ky*3 + kx)*CO_T];
                    unsigned long long w2[8];
                    #pragma unroll
                    for (int j = 0; j < 8; j++) w2[j] = wp[j];
                    #pragma unroll
                    for (int p = 0; p < 4; p++){
                        unsigned long long xx = pack2(xv[kx + p], xv[kx + p]);
                        #pragma unroll
                        for (int j = 0; j < 8; j++) fma2(acc[p][j], w2[j], xx);
                    }
                }
            }
        }
    }

    // store: per j, gather 4 consecutive px into float4 (coalesced)
    int y = y0 + py;
    float* ob = g_fuse + (size_t)b*C*PLANE + (size_t)y*HWD + px0;
    #pragma unroll
    for (int j = 0; j < 8; j++){
        float lo[4], hi[4];
        #pragma unroll
        for (int p = 0; p < 4; p++) unpack2(acc[p][j], lo[p], hi[p]);
        float4 v0 = make_float4(lo[0], lo[1], lo[2], lo[3]);
        float4 v1 = make_float4(hi[0], hi[1], hi[2], hi[3]);
        *(float4*)(ob + (size_t)(co0 + 2*j    )*PLANE) = v0;
        *(float4*)(ob + (size_t)(co0 + 2*j + 1)*PLANE) = v1;
    }
}

// ---------------- final gated sum ----------------
__global__ void k_final(const float* __restrict__ dten, float* __restrict__ out){
    size_t i = (size_t)blockIdx.x*256 + threadIdx.x;   // float4 index
    size_t e = i * 4;
    int bc = (int)(e >> 14);        // [b][c] plane index (plane = 16384)
    float gf = g_gf[bc];
    float gd = g_gd[bc];
    float4 f4 = *(const float4*)(g_fuse + e);
    float4 d4 = *(const float4*)(dten + e);
    float4 o;
    o.x = f4.x*gf + d4.x*gd;
    o.y = f4.y*gf + d4.y*gd;
    o.z = f4.z*gf + d4.z*gd;
    o.w = f4.w*gf + d4.w*gd;
    *(float4*)(out + e) = o;
}

// ---------------- launch ----------------
extern "C" void kernel_launch(void* const* d_in, const int* in_sizes, int n_in,
                              void* d_out, int out_size){
    const float* r      = (const float*)d_in[0];
    const float* d      = (const float*)d_in[1];
    const int*   label  = (const int*)  d_in[2];
    const float* conv_w = (const float*)d_in[3];
    const float* f_w1   = (const float*)d_in[4];
    const float* f_w2   = (const float*)d_in[5];
    const float* d_w1   = (const float*)d_in[6];
    const float* d_w2   = (const float*)d_in[7];
    const float* base_f = (const float*)d_in[8];
    const float* base_d = (const float*)d_in[9];
    float* out = (float*)d_out;

    k_zero<<<(B*L*C + 255)/256, 256>>>();

    dim3 segGrid(8, B);
    k_seg<<<segGrid, 256>>>(d, label, 0);            // d-pass (+counts)
    k_gate<<<B, 128>>>(0, base_d, d_w1, d_w2);       // -> g_gd

    dim3 convGrid(16, 8, B);
    k_conv<<<convGrid, 256>>>(r, d, conv_w);         // -> g_fuse

    k_seg<<<segGrid, 256>>>(d, label, 1);            // fuse-pass (reads g_fuse)
    k_gate<<<B, 128>>>(1, base_f, f_w1, f_w2);       // -> g_gf

    k_final<<<(B*C*PLANE/4 + 255)/256, 256>>>(d, out);
}